// round 2
// baseline (speedup 1.0000x reference)
#include <cuda_runtime.h>
#include <cstdint>

// Problem constants (fixed by the dataset)
#define N_NODES 50000
#define N_EDGES 800000
#define FDIM 64
#define LDIM 4
#define RDIM 8
#define HDIM 64
#define INV_AVG_NEIGH (1.0f / 16.0f)

// Scratch (allocation-free rule: __device__ globals)
__device__ float g_x[N_NODES * FDIM];    // node_features @ W_up
__device__ float g_agg[N_NODES * FDIM];  // scatter accumulator

__device__ __forceinline__ float swishf(float x) {
    return x / (1.0f + __expf(-x));
}

__device__ __forceinline__ float4 fma4(float s, float4 w, float4 acc) {
    acc.x = fmaf(s, w.x, acc.x);
    acc.y = fmaf(s, w.y, acc.y);
    acc.z = fmaf(s, w.z, acc.z);
    acc.w = fmaf(s, w.w, acc.w);
    return acc;
}

__device__ __forceinline__ void red_add_f4(float4* addr, float4 v) {
    asm volatile("red.global.add.v4.f32 [%0], {%1, %2, %3, %4};"
                 :: "l"(addr), "f"(v.x), "f"(v.y), "f"(v.z), "f"(v.w)
                 : "memory");
}

// ---------------------------------------------------------------------------
// Zero the aggregation buffer (must be re-zeroed on every graph replay)
// ---------------------------------------------------------------------------
__global__ void zero_agg_kernel() {
    int i = blockIdx.x * blockDim.x + threadIdx.x;  // grid sized exactly in f4
    float4* p = reinterpret_cast<float4*>(g_agg);
    p[i] = make_float4(0.f, 0.f, 0.f, 0.f);
}

// ---------------------------------------------------------------------------
// Y[row,:] = (scale * X[row,:]) @ W   for 64x64 W. One row per thread,
// W staged in shared (uniform broadcast reads).
// ---------------------------------------------------------------------------
__global__ void linear64_kernel(const float* __restrict__ X,
                                const float* __restrict__ W,
                                float* __restrict__ Y,
                                int n, float scale) {
    __shared__ float4 sW[64 * 16];
    for (int i = threadIdx.x; i < 64 * 16; i += blockDim.x)
        sW[i] = reinterpret_cast<const float4*>(W)[i];
    __syncthreads();

    int row = blockIdx.x * blockDim.x + threadIdx.x;
    if (row >= n) return;

    const float4* xr = reinterpret_cast<const float4*>(X + (size_t)row * 64);
    float xv[64];
#pragma unroll
    for (int i = 0; i < 16; i++) {
        float4 v = xr[i];
        xv[4 * i + 0] = v.x * scale;
        xv[4 * i + 1] = v.y * scale;
        xv[4 * i + 2] = v.z * scale;
        xv[4 * i + 3] = v.w * scale;
    }

    float4 acc[16];
#pragma unroll
    for (int j = 0; j < 16; j++) acc[j] = make_float4(0.f, 0.f, 0.f, 0.f);

#pragma unroll
    for (int k = 0; k < 64; k++) {
        float xk = xv[k];
#pragma unroll
        for (int j = 0; j < 16; j++)
            acc[j] = fma4(xk, sW[k * 16 + j], acc[j]);
    }

    float4* yr = reinterpret_cast<float4*>(Y + (size_t)row * 64);
#pragma unroll
    for (int j = 0; j < 16; j++) yr[j] = acc[j];
}

// ---------------------------------------------------------------------------
// Fused edge kernel: radial MLP (swish/swish) -> W3 contraction fused with
// edge_features dot -> multiply with gathered sender features -> vector
// red.global into g_agg[receiver].
// Weights in dynamic shared (2KB + 16KB + 64KB = 82KB). One edge per thread.
// NOTE: edge_mask is jnp.bool_ but the harness materializes it as int32
// (confirmed by rel_err == sqrt(3/4) when read as bytes).
// ---------------------------------------------------------------------------
__global__ void __launch_bounds__(256, 1)
edge_kernel(const float* __restrict__ edge_features,   // [E,4]
            const float* __restrict__ radial,          // [E,8]
            const int* __restrict__ senders,
            const int* __restrict__ receivers,
            const int* __restrict__ mask,               // int32 bool
            const float* __restrict__ W1,               // [8,64]
            const float* __restrict__ W2,               // [64,64]
            const float* __restrict__ W3) {             // [64,256]
    extern __shared__ float4 smem[];
    float4* sW1 = smem;             // 128 float4
    float4* sW2 = smem + 128;       // 1024 float4
    float4* sW3 = smem + 128 + 1024;// 4096 float4: sW3[k*64+f] = W3[k][4f..4f+3]

    for (int i = threadIdx.x; i < 128; i += 256)
        sW1[i] = reinterpret_cast<const float4*>(W1)[i];
    for (int i = threadIdx.x; i < 1024; i += 256)
        sW2[i] = reinterpret_cast<const float4*>(W2)[i];
    for (int i = threadIdx.x; i < 4096; i += 256)
        sW3[i] = reinterpret_cast<const float4*>(W3)[i];
    __syncthreads();

    int e = blockIdx.x * blockDim.x + threadIdx.x;
    if (e >= N_EDGES) return;
    if (mask[e] == 0) return;

    // ---- layer 1: h1 = swish(r @ W1) ----
    const float4* rv = reinterpret_cast<const float4*>(radial + (size_t)e * 8);
    float4 r0 = rv[0], r1 = rv[1];
    float rr[8] = {r0.x, r0.y, r0.z, r0.w, r1.x, r1.y, r1.z, r1.w};

    float4 a[16];
#pragma unroll
    for (int j = 0; j < 16; j++) a[j] = make_float4(0.f, 0.f, 0.f, 0.f);
#pragma unroll
    for (int i = 0; i < 8; i++) {
        float ri = rr[i];
#pragma unroll
        for (int j = 0; j < 16; j++)
            a[j] = fma4(ri, sW1[i * 16 + j], a[j]);
    }
    float h1[64];
#pragma unroll
    for (int j = 0; j < 16; j++) {
        h1[4 * j + 0] = swishf(a[j].x);
        h1[4 * j + 1] = swishf(a[j].y);
        h1[4 * j + 2] = swishf(a[j].z);
        h1[4 * j + 3] = swishf(a[j].w);
    }

    // ---- layer 2: h2 = swish(h1 @ W2) ----
    float4 b[16];
#pragma unroll
    for (int j = 0; j < 16; j++) b[j] = make_float4(0.f, 0.f, 0.f, 0.f);
#pragma unroll
    for (int k = 0; k < 64; k++) {
        float hk = h1[k];
#pragma unroll
        for (int j = 0; j < 16; j++)
            b[j] = fma4(hk, sW2[k * 16 + j], b[j]);
    }
    float h2[64];
#pragma unroll
    for (int j = 0; j < 16; j++) {
        h2[4 * j + 0] = swishf(b[j].x);
        h2[4 * j + 1] = swishf(b[j].y);
        h2[4 * j + 2] = swishf(b[j].z);
        h2[4 * j + 3] = swishf(b[j].w);
    }

    // ---- message: msg[f] = x_s[f] * sum_l ef[l] * (h2 @ W3)[f,l] ----
    float4 efv = *reinterpret_cast<const float4*>(edge_features + (size_t)e * 4);
    int s = senders[e];
    int rcv = receivers[e];
    const float4* xrow = reinterpret_cast<const float4*>(g_x + (size_t)s * 64);
    float4* arow = reinterpret_cast<float4*>(g_agg + (size_t)rcv * 64);

#pragma unroll 1
    for (int f4 = 0; f4 < 16; f4++) {
        // U[t] accumulates (h2 @ W3) for f = 4*f4+t, over l = 0..3
        float4 U0 = make_float4(0.f, 0.f, 0.f, 0.f);
        float4 U1 = U0, U2 = U0, U3 = U0;
#pragma unroll
        for (int k = 0; k < 64; k++) {
            float hk = h2[k];
            const float4* w3r = sW3 + k * 64 + f4 * 4;
            U0 = fma4(hk, w3r[0], U0);
            U1 = fma4(hk, w3r[1], U1);
            U2 = fma4(hk, w3r[2], U2);
            U3 = fma4(hk, w3r[3], U3);
        }
        float in0 = fmaf(efv.w, U0.w, fmaf(efv.z, U0.z, fmaf(efv.y, U0.y, efv.x * U0.x)));
        float in1 = fmaf(efv.w, U1.w, fmaf(efv.z, U1.z, fmaf(efv.y, U1.y, efv.x * U1.x)));
        float in2 = fmaf(efv.w, U2.w, fmaf(efv.z, U2.z, fmaf(efv.y, U2.y, efv.x * U2.x)));
        float in3 = fmaf(efv.w, U3.w, fmaf(efv.z, U3.z, fmaf(efv.y, U3.y, efv.x * U3.x)));

        float4 xs = xrow[f4];
        float4 m = make_float4(xs.x * in0, xs.y * in1, xs.z * in2, xs.w * in3);
        red_add_f4(arow + f4, m);
    }
}

// ---------------------------------------------------------------------------
// kernel_launch
// Input order: node_features, edge_features, radial_embedding, senders,
//              receivers, edge_mask, W_up, W1, W2, W3, W_down
// ---------------------------------------------------------------------------
extern "C" void kernel_launch(void* const* d_in, const int* in_sizes, int n_in,
                              void* d_out, int out_size) {
    const float*   node_features = (const float*)d_in[0];
    const float*   edge_features = (const float*)d_in[1];
    const float*   radial        = (const float*)d_in[2];
    const int*     senders       = (const int*)d_in[3];
    const int*     receivers     = (const int*)d_in[4];
    const int*     edge_mask     = (const int*)d_in[5];
    const float*   W_up          = (const float*)d_in[6];
    const float*   W1            = (const float*)d_in[7];
    const float*   W2            = (const float*)d_in[8];
    const float*   W3            = (const float*)d_in[9];
    const float*   W_down        = (const float*)d_in[10];
    float*         out           = (float*)d_out;

    float* x_ptr = nullptr;
    float* agg_ptr = nullptr;
    cudaGetSymbolAddress((void**)&x_ptr, g_x);
    cudaGetSymbolAddress((void**)&agg_ptr, g_agg);

    // 1) x = node_features @ W_up
    linear64_kernel<<<(N_NODES + 127) / 128, 128>>>(node_features, W_up, x_ptr,
                                                    N_NODES, 1.0f);

    // 2) zero agg (exact grid: N_NODES*FDIM/4 float4 = 800000 -> 3125 * 256)
    zero_agg_kernel<<<(N_NODES * FDIM / 4) / 256, 256>>>();

    // 3) fused edge MLP + message + scatter
    static const size_t SMEM_BYTES = (128 + 1024 + 4096) * sizeof(float4); // 83968
    cudaFuncSetAttribute(edge_kernel, cudaFuncAttributeMaxDynamicSharedMemorySize,
                         (int)SMEM_BYTES);
    edge_kernel<<<(N_EDGES + 255) / 256, 256, SMEM_BYTES>>>(
        edge_features, radial, senders, receivers, edge_mask, W1, W2, W3);

    // 4) out = (agg / 16) @ W_down
    linear64_kernel<<<(N_NODES + 127) / 128, 128>>>(agg_ptr, W_down, out,
                                                    N_NODES, INV_AVG_NEIGH);
}

// round 4
// speedup vs baseline: 1.5962x; 1.5962x over previous
#include <cuda_runtime.h>
#include <cstdint>

// Problem constants (fixed by the dataset)
#define N_NODES 50000
#define N_EDGES 800000
#define FDIM 64
#define LDIM 4
#define RDIM 8
#define HDIM 64
#define INV_AVG_NEIGH (1.0f / 16.0f)

// Scratch (allocation-free rule: __device__ globals)
__device__ float g_x[N_NODES * FDIM];    // node_features @ W_up
__device__ float g_agg[N_NODES * FDIM];  // scatter accumulator

__device__ __forceinline__ float swishf(float x) {
    return x / (1.0f + __expf(-x));
}
__device__ __forceinline__ float4 fma4(float s, float4 w, float4 acc) {
    acc.x = fmaf(s, w.x, acc.x);
    acc.y = fmaf(s, w.y, acc.y);
    acc.z = fmaf(s, w.z, acc.z);
    acc.w = fmaf(s, w.w, acc.w);
    return acc;
}
__device__ __forceinline__ float tf32_rna(float x) {
    uint32_t u;
    asm("cvt.rna.tf32.f32 %0, %1;" : "=r"(u) : "f"(x));
    return __uint_as_float(u);
}
__device__ __forceinline__ uint32_t tf32_bits(float x) {
    uint32_t u;
    asm("cvt.rna.tf32.f32 %0, %1;" : "=r"(u) : "f"(x));
    return u;
}
__device__ __forceinline__ void red_add_f2(float* addr, float v0, float v1) {
    asm volatile("red.global.add.v2.f32 [%0], {%1, %2};"
                 :: "l"(addr), "f"(v0), "f"(v1) : "memory");
}
__device__ __forceinline__ void red_add_f4(float4* addr, float4 v) {
    asm volatile("red.global.add.v4.f32 [%0], {%1, %2, %3, %4};"
                 :: "l"(addr), "f"(v.x), "f"(v.y), "f"(v.z), "f"(v.w)
                 : "memory");
}

// mma.sync m16n8k8 tf32: D[16,8] += A[16,8] * B[8,8]   (row.col)
__device__ __forceinline__ void mma_tf32(float* d, const uint32_t* a,
                                         const uint32_t* b) {
    asm volatile(
        "mma.sync.aligned.m16n8k8.row.col.f32.tf32.tf32.f32 "
        "{%0,%1,%2,%3}, {%4,%5,%6,%7}, {%8,%9}, {%0,%1,%2,%3};"
        : "+f"(d[0]), "+f"(d[1]), "+f"(d[2]), "+f"(d[3])
        : "r"(a[0]), "r"(a[1]), "r"(a[2]), "r"(a[3]), "r"(b[0]), "r"(b[1]));
}

// ---------------------------------------------------------------------------
// Zero the aggregation buffer (re-zeroed on every graph replay)
// ---------------------------------------------------------------------------
__global__ void zero_agg_kernel() {
    int i = blockIdx.x * blockDim.x + threadIdx.x;
    reinterpret_cast<float4*>(g_agg)[i] = make_float4(0.f, 0.f, 0.f, 0.f);
}

// ---------------------------------------------------------------------------
// Y[row,:] = (scale * X[row,:]) @ W for 64x64 W. One row per thread.
// ---------------------------------------------------------------------------
__global__ void linear64_kernel(const float* __restrict__ X,
                                const float* __restrict__ W,
                                float* __restrict__ Y,
                                int n, float scale) {
    __shared__ float4 sW[64 * 16];
    for (int i = threadIdx.x; i < 64 * 16; i += blockDim.x)
        sW[i] = reinterpret_cast<const float4*>(W)[i];
    __syncthreads();

    int row = blockIdx.x * blockDim.x + threadIdx.x;
    if (row >= n) return;

    const float4* xr = reinterpret_cast<const float4*>(X + (size_t)row * 64);
    float xv[64];
#pragma unroll
    for (int i = 0; i < 16; i++) {
        float4 v = xr[i];
        xv[4 * i + 0] = v.x * scale;
        xv[4 * i + 1] = v.y * scale;
        xv[4 * i + 2] = v.z * scale;
        xv[4 * i + 3] = v.w * scale;
    }
    float4 acc[16];
#pragma unroll
    for (int j = 0; j < 16; j++) acc[j] = make_float4(0.f, 0.f, 0.f, 0.f);
#pragma unroll
    for (int k = 0; k < 64; k++) {
        float xk = xv[k];
#pragma unroll
        for (int j = 0; j < 16; j++)
            acc[j] = fma4(xk, sW[k * 16 + j], acc[j]);
    }
    float4* yr = reinterpret_cast<float4*>(Y + (size_t)row * 64);
#pragma unroll
    for (int j = 0; j < 16; j++) yr[j] = acc[j];
}

// ---------------------------------------------------------------------------
// Fused edge kernel, W3 contraction on mma.sync tf32 tensor cores.
//
// 256 threads / 256 edges per CTA. CUDA-core radial MLP -> h2 (tf32-rounded)
// staged in shared [256][65]. Implicit A operand G[e, k*4+l] = h2[e,k]*ef[e,l]
// built per-fragment in registers. B = W3'[f][kl] = W3[kl>>2][4f+(kl&3)]
// staged tf32 in shared [64][260] (pad 260 -> conflict-free frag loads).
// Each warp: D[32 edges, 64 f] via 512x mma.m16n8k8, K=256.
// Epilogue: per-fragment x_s gather + red.global.add.v2 scatter.
// ---------------------------------------------------------------------------
#define TILE 256
#define PADH 65
#define PADB 260
#define SB_FLOATS (64 * PADB)                    // 16640
#define SH_FLOATS (TILE * PADH)                  // 16640
#define EDGE_SMEM ((SB_FLOATS + SH_FLOATS) * 4 + 2048 + 16384)  // 151552 B

__global__ void __launch_bounds__(256, 1)
edge_kernel(const float* __restrict__ edge_features,   // [E,4]
            const float* __restrict__ radial,          // [E,8]
            const int* __restrict__ senders,
            const int* __restrict__ receivers,
            const int* __restrict__ mask,               // int32 bool
            const float* __restrict__ W1,               // [8,64]
            const float* __restrict__ W2,               // [64,64]
            const float* __restrict__ W3) {             // [64,256]
    extern __shared__ float smem[];
    float* sB = smem;                       // [64][260]
    float* sH = smem + SB_FLOATS;           // [256][65]
    float4* sW1 = reinterpret_cast<float4*>(sH + SH_FLOATS);  // 128 f4
    float4* sW2 = sW1 + 128;                                  // 1024 f4

    int tid = threadIdx.x;
    int wid = tid >> 5;
    int lane = tid & 31;
    int g = lane >> 2;       // groupID (0-7)
    int tig = lane & 3;      // threadID_in_group (0-3)

    // ---- stage weights + B ----
    for (int i = tid; i < 128; i += 256)
        sW1[i] = reinterpret_cast<const float4*>(W1)[i];
    for (int i = tid; i < 1024; i += 256)
        sW2[i] = reinterpret_cast<const float4*>(W2)[i];
    for (int idx = tid; idx < 64 * 256; idx += 256) {
        int f = idx >> 8;
        int kl = idx & 255;
        int k = kl >> 2, l = kl & 3;
        sB[f * PADB + kl] = tf32_rna(W3[k * 256 + f * 4 + l]);
    }
    __syncthreads();

    // ---- per-edge radial MLP (CUDA cores), edge e = this thread ----
    int e = blockIdx.x * TILE + tid;   // grid exact: 800000/256 = 3125
    const float4* rv = reinterpret_cast<const float4*>(radial + (size_t)e * 8);
    float4 r0 = rv[0], r1 = rv[1];
    float rr[8] = {r0.x, r0.y, r0.z, r0.w, r1.x, r1.y, r1.z, r1.w};

    float4 a[16];
#pragma unroll
    for (int j = 0; j < 16; j++) a[j] = make_float4(0.f, 0.f, 0.f, 0.f);
#pragma unroll
    for (int i = 0; i < 8; i++) {
        float ri = rr[i];
#pragma unroll
        for (int j = 0; j < 16; j++)
            a[j] = fma4(ri, sW1[i * 16 + j], a[j]);
    }
    float h1[64];
#pragma unroll
    for (int j = 0; j < 16; j++) {
        h1[4 * j + 0] = swishf(a[j].x);
        h1[4 * j + 1] = swishf(a[j].y);
        h1[4 * j + 2] = swishf(a[j].z);
        h1[4 * j + 3] = swishf(a[j].w);
    }
    float4 b[16];
#pragma unroll
    for (int j = 0; j < 16; j++) b[j] = make_float4(0.f, 0.f, 0.f, 0.f);
#pragma unroll
    for (int k = 0; k < 64; k++) {
        float hk = h1[k];
#pragma unroll
        for (int j = 0; j < 16; j++)
            b[j] = fma4(hk, sW2[k * 16 + j], b[j]);
    }
    // h2 -> shared, tf32-rounded
    float* hrow = sH + tid * PADH;
#pragma unroll
    for (int j = 0; j < 16; j++) {
        hrow[4 * j + 0] = tf32_rna(swishf(b[j].x));
        hrow[4 * j + 1] = tf32_rna(swishf(b[j].y));
        hrow[4 * j + 2] = tf32_rna(swishf(b[j].z));
        hrow[4 * j + 3] = tf32_rna(swishf(b[j].w));
    }
    __syncwarp();   // this warp's 32 rows are read only by this warp

    // ---- fragment-row metadata (rows g, g+8, g+16, g+24 of warp tile) ----
    int ebase = blockIdx.x * TILE + wid * 32;
    float efr[4];
    int snd[4], rcv[4], mk[4];
#pragma unroll
    for (int ri = 0; ri < 4; ri++) {
        int row = g + ri * 8;
        int e2 = ebase + row;
        efr[ri] = tf32_rna(edge_features[(size_t)e2 * 4 + tig]);
        snd[ri] = senders[e2];
        rcv[ri] = receivers[e2];
        mk[ri] = mask[e2];
    }
    const float* h0 = sH + (wid * 32 + g) * PADH;          // row g
    const float* h1p = h0 + 8 * PADH;                      // row g+8
    const float* h2p = h0 + 16 * PADH;                     // row g+16
    const float* h3p = h0 + 24 * PADH;                     // row g+24

    // ---- warp GEMM: D[32,64] = G[32,256] @ W3'[256,64] ----
    float d[2][8][4];
#pragma unroll
    for (int mt = 0; mt < 2; mt++)
#pragma unroll
        for (int nt = 0; nt < 8; nt++)
#pragma unroll
            for (int q = 0; q < 4; q++) d[mt][nt][q] = 0.f;

#pragma unroll 1
    for (int kt = 0; kt < 32; kt++) {
        int k0 = 2 * kt;
        // A fragments: col tig -> kl = 8kt+tig -> (k=2kt, l=tig);
        //              col tig+4 -> (k=2kt+1, l=tig)
        uint32_t A0[4], A1[4];
        A0[0] = tf32_bits(h0[k0] * efr[0]);
        A0[1] = tf32_bits(h1p[k0] * efr[1]);
        A0[2] = tf32_bits(h0[k0 + 1] * efr[0]);
        A0[3] = tf32_bits(h1p[k0 + 1] * efr[1]);
        A1[0] = tf32_bits(h2p[k0] * efr[2]);
        A1[1] = tf32_bits(h3p[k0] * efr[2 + 1]);
        A1[2] = tf32_bits(h2p[k0 + 1] * efr[2]);
        A1[3] = tf32_bits(h3p[k0 + 1] * efr[3]);

        const float* bp = sB + kt * 8 + tig;
#pragma unroll
        for (int nt = 0; nt < 8; nt++) {
            uint32_t B[2];
            const float* bn = bp + (nt * 8 + g) * PADB;
            B[0] = __float_as_uint(bn[0]);
            B[1] = __float_as_uint(bn[4]);
            mma_tf32(d[0][nt], A0, B);
            mma_tf32(d[1][nt], A1, B);
        }
    }

    // ---- epilogue: msg = D * x_s[senders], red-scatter to g_agg ----
#pragma unroll
    for (int ri = 0; ri < 4; ri++) {
        if (!mk[ri]) continue;
        int mt = ri >> 1, hi = ri & 1;
        const float* xr = g_x + (size_t)snd[ri] * 64;
        float* ar = g_agg + (size_t)rcv[ri] * 64;
#pragma unroll
        for (int nt = 0; nt < 8; nt++) {
            int c = nt * 8 + 2 * tig;
            float2 xs = *reinterpret_cast<const float2*>(xr + c);
            red_add_f2(ar + c, d[mt][nt][2 * hi] * xs.x,
                               d[mt][nt][2 * hi + 1] * xs.y);
        }
    }
}

// ---------------------------------------------------------------------------
// kernel_launch
// Input order: node_features, edge_features, radial_embedding, senders,
//              receivers, edge_mask, W_up, W1, W2, W3, W_down
// ---------------------------------------------------------------------------
extern "C" void kernel_launch(void* const* d_in, const int* in_sizes, int n_in,
                              void* d_out, int out_size) {
    const float* node_features = (const float*)d_in[0];
    const float* edge_features = (const float*)d_in[1];
    const float* radial        = (const float*)d_in[2];
    const int*   senders       = (const int*)d_in[3];
    const int*   receivers     = (const int*)d_in[4];
    const int*   edge_mask     = (const int*)d_in[5];
    const float* W_up          = (const float*)d_in[6];
    const float* W1            = (const float*)d_in[7];
    const float* W2            = (const float*)d_in[8];
    const float* W3            = (const float*)d_in[9];
    const float* W_down        = (const float*)d_in[10];
    float*       out           = (float*)d_out;

    float* x_ptr = nullptr;
    float* agg_ptr = nullptr;
    cudaGetSymbolAddress((void**)&x_ptr, g_x);
    cudaGetSymbolAddress((void**)&agg_ptr, g_agg);

    // 1) x = node_features @ W_up
    linear64_kernel<<<(N_NODES + 127) / 128, 128>>>(node_features, W_up, x_ptr,
                                                    N_NODES, 1.0f);
    // 2) zero agg
    zero_agg_kernel<<<(N_NODES * FDIM / 4) / 256, 256>>>();

    // 3) fused edge kernel (mma.sync tf32 W3 path)
    cudaFuncSetAttribute(edge_kernel, cudaFuncAttributeMaxDynamicSharedMemorySize,
                         EDGE_SMEM);
    edge_kernel<<<N_EDGES / TILE, TILE, EDGE_SMEM>>>(
        edge_features, radial, senders, receivers, edge_mask, W1, W2, W3);

    // 4) out = (agg / 16) @ W_down
    linear64_kernel<<<(N_NODES + 127) / 128, 128>>>(agg_ptr, W_down, out,
                                                    N_NODES, INV_AVG_NEIGH);
}

// round 5
// speedup vs baseline: 2.9682x; 1.8595x over previous
#include <cuda_runtime.h>
#include <cstdint>

#define N_NODES 50000
#define N_EDGES 800000
#define FDIM 64
#define INV_AVG_NEIGH (1.0f / 16.0f)

__device__ float g_x[N_NODES * FDIM];
__device__ float g_agg[N_NODES * FDIM];

__device__ __forceinline__ float swishf(float x) {
    return x / (1.0f + __expf(-x));
}
__device__ __forceinline__ float4 fma4(float s, float4 w, float4 acc) {
    acc.x = fmaf(s, w.x, acc.x);
    acc.y = fmaf(s, w.y, acc.y);
    acc.z = fmaf(s, w.z, acc.z);
    acc.w = fmaf(s, w.w, acc.w);
    return acc;
}
__device__ __forceinline__ float tf32_rna(float x) {
    uint32_t u;
    asm("cvt.rna.tf32.f32 %0, %1;" : "=r"(u) : "f"(x));
    return __uint_as_float(u);
}
__device__ __forceinline__ uint32_t tf32_bits(float x) {
    uint32_t u;
    asm("cvt.rna.tf32.f32 %0, %1;" : "=r"(u) : "f"(x));
    return u;
}
__device__ __forceinline__ void red_add_f2(float* addr, float v0, float v1) {
    asm volatile("red.global.add.v2.f32 [%0], {%1, %2};"
                 :: "l"(addr), "f"(v0), "f"(v1) : "memory");
}

// mma.sync m16n8k8 tf32 row.col: D[16,8] += A[16,8] * B[8,8]^T
__device__ __forceinline__ void mma_tf32(float* d, const uint32_t* a,
                                         const uint32_t* b) {
    asm volatile(
        "mma.sync.aligned.m16n8k8.row.col.f32.tf32.tf32.f32 "
        "{%0,%1,%2,%3}, {%4,%5,%6,%7}, {%8,%9}, {%0,%1,%2,%3};"
        : "+f"(d[0]), "+f"(d[1]), "+f"(d[2]), "+f"(d[3])
        : "r"(a[0]), "r"(a[1]), "r"(a[2]), "r"(a[3]), "r"(b[0]), "r"(b[1]));
}

__global__ void noop_kernel() {}

__global__ void zero_agg_kernel() {
    int i = blockIdx.x * blockDim.x + threadIdx.x;
    reinterpret_cast<float4*>(g_agg)[i] = make_float4(0.f, 0.f, 0.f, 0.f);
}

// Y[row,:] = (scale * X[row,:]) @ W  (64x64). One row per thread.
__global__ void linear64_kernel(const float* __restrict__ X,
                                const float* __restrict__ W,
                                float* __restrict__ Y,
                                int n, float scale) {
    __shared__ float4 sW[64 * 16];
    for (int i = threadIdx.x; i < 64 * 16; i += blockDim.x)
        sW[i] = reinterpret_cast<const float4*>(W)[i];
    __syncthreads();

    int row = blockIdx.x * blockDim.x + threadIdx.x;
    if (row >= n) return;

    const float4* xr = reinterpret_cast<const float4*>(X + (size_t)row * 64);
    float xv[64];
#pragma unroll
    for (int i = 0; i < 16; i++) {
        float4 v = xr[i];
        xv[4 * i + 0] = v.x * scale;
        xv[4 * i + 1] = v.y * scale;
        xv[4 * i + 2] = v.z * scale;
        xv[4 * i + 3] = v.w * scale;
    }
    float4 acc[16];
#pragma unroll
    for (int j = 0; j < 16; j++) acc[j] = make_float4(0.f, 0.f, 0.f, 0.f);
#pragma unroll
    for (int k = 0; k < 64; k++) {
        float xk = xv[k];
#pragma unroll
        for (int j = 0; j < 16; j++)
            acc[j] = fma4(xk, sW[k * 16 + j], acc[j]);
    }
    float4* yr = reinterpret_cast<float4*>(Y + (size_t)row * 64);
#pragma unroll
    for (int j = 0; j < 16; j++) yr[j] = acc[j];
}

// ---------------------------------------------------------------------------
// Fused edge kernel, fully tensorized W2 and W3 contractions.
// CTA: 512 threads, 256 edges. Warp w owns edges [16w, 16w+16) (M=16 tiles).
//  L1 (scalar): 2 threads/edge compute 32 h1-cols each -> tf32 -> sH1.
//  L2 (mma):    h2_pre = h1 @ W2 via 64x m16n8k8 (K=64), swish in regs.
//  W3 (mma):    D = G @ W3', G[e,8kt+tig] rebuilt per kt via 4 shfl from the
//               W2 D-fragments (register index kt>>2 is unroll-constant,
//               src lane 4g+(kt&3)) times ef (l = tig).
//  Epilogue:    msg = D * x[senders], red.global.v2 -> g_agg[receivers].
// ---------------------------------------------------------------------------
#define TILE_E 256
#define NTH 512
#define PAD 68
#define PADB 260
// smem (floats): sB[64*260] | sH1[256*68] | sW2t[64*68] | sW1[128 f4]
#define OFF_H1  (64 * PADB)
#define OFF_W2T (OFF_H1 + 256 * PAD)
#define OFF_W1  (OFF_W2T + 64 * PAD)
#define EDGE_SMEM ((OFF_W1 + 128 * 4) * 4)   // 155648 B

__global__ void __launch_bounds__(NTH, 1)
edge_kernel(const float* __restrict__ edge_features,   // [E,4]
            const float* __restrict__ radial,          // [E,8]
            const int* __restrict__ senders,
            const int* __restrict__ receivers,
            const int* __restrict__ mask,               // int32 bool
            const float* __restrict__ W1,               // [8,64]
            const float* __restrict__ W2,               // [64,64]
            const float* __restrict__ W3) {             // [64,256]
    extern __shared__ float smem[];
    float* sB   = smem;                  // [64][260]  W3'[f][kl]
    float* sH1  = smem + OFF_H1;         // [256][68]  h1 (tf32)
    float* sW2t = smem + OFF_W2T;        // [64][68]   W2^T[n][k]
    float4* sW1 = reinterpret_cast<float4*>(smem + OFF_W1);  // [8][16 f4]

    int tid = threadIdx.x;
    int base = blockIdx.x * TILE_E;

    // ---- stage weights (tf32-rounded for mma operands) ----
    for (int i = tid; i < 128; i += NTH)
        sW1[i] = reinterpret_cast<const float4*>(W1)[i];
    for (int idx = tid; idx < 64 * 64; idx += NTH) {
        int k = idx >> 6, n = idx & 63;          // coalesced W2 read
        sW2t[n * PAD + k] = tf32_rna(W2[k * 64 + n]);
    }
    for (int idx = tid; idx < 64 * 256; idx += NTH) {
        int f = idx >> 8, kl = idx & 255;
        sB[f * PADB + kl] = tf32_rna(W3[(kl >> 2) * 256 + f * 4 + (kl & 3)]);
    }

    // ---- L1 scalar: 2 threads per edge, 32 cols each ----
    {
        int e_loc = tid & 255;
        int half = tid >> 8;
        const float4* rv =
            reinterpret_cast<const float4*>(radial + (size_t)(base + e_loc) * 8);
        float4 r0 = rv[0], r1 = rv[1];
        float rr[8] = {r0.x, r0.y, r0.z, r0.w, r1.x, r1.y, r1.z, r1.w};

        float4 a[8];
#pragma unroll
        for (int j = 0; j < 8; j++) a[j] = make_float4(0.f, 0.f, 0.f, 0.f);
#pragma unroll
        for (int i = 0; i < 8; i++) {
            float ri = rr[i];
#pragma unroll
            for (int j = 0; j < 8; j++)
                a[j] = fma4(ri, sW1[i * 16 + half * 8 + j], a[j]);
        }
        float4* hrow =
            reinterpret_cast<float4*>(sH1 + e_loc * PAD + half * 32);
#pragma unroll
        for (int j = 0; j < 8; j++) {
            float4 o;
            o.x = tf32_rna(swishf(a[j].x));
            o.y = tf32_rna(swishf(a[j].y));
            o.z = tf32_rna(swishf(a[j].z));
            o.w = tf32_rna(swishf(a[j].w));
            hrow[j] = o;
        }
    }
    __syncthreads();

    // ---- GEMM phase: warp w owns 16 edges ----
    int w = tid >> 5, lane = tid & 31;
    int g = lane >> 2, tig = lane & 3;
    int e0 = base + 16 * w + g;
    int e1 = e0 + 8;

    float ef0 = edge_features[(size_t)e0 * 4 + tig];
    float ef1 = edge_features[(size_t)e1 * 4 + tig];
    int snd0 = senders[e0], snd1 = senders[e1];
    int rcv0 = receivers[e0], rcv1 = receivers[e1];
    int mk0 = mask[e0], mk1 = mask[e1];

    // L2: d2 = h1 @ W2  (K=64, 64 mma)
    float d2[8][4];
#pragma unroll
    for (int nt = 0; nt < 8; nt++)
#pragma unroll
        for (int q = 0; q < 4; q++) d2[nt][q] = 0.f;

    const uint32_t* sH1u = reinterpret_cast<const uint32_t*>(sH1);
    const uint32_t* sW2u = reinterpret_cast<const uint32_t*>(sW2t);
#pragma unroll
    for (int kt = 0; kt < 8; kt++) {
        uint32_t A[4];
        const uint32_t* h0 = sH1u + (16 * w + g) * PAD + 8 * kt + tig;
        A[0] = h0[0];
        A[1] = h0[8 * PAD];
        A[2] = h0[4];
        A[3] = h0[8 * PAD + 4];
#pragma unroll
        for (int nt = 0; nt < 8; nt++) {
            uint32_t B[2];
            const uint32_t* bp = sW2u + (8 * nt + g) * PAD + 8 * kt + tig;
            B[0] = bp[0];
            B[1] = bp[4];
            mma_tf32(d2[nt], A, B);
        }
    }
    // swish -> h2 (f32, stays in D-fragment layout)
#pragma unroll
    for (int nt = 0; nt < 8; nt++)
#pragma unroll
        for (int q = 0; q < 4; q++) d2[nt][q] = swishf(d2[nt][q]);

    // W3: d3 = G @ W3'  (K=256, 256 mma), A via shfl from d2
    float d3[8][4];
#pragma unroll
    for (int nt = 0; nt < 8; nt++)
#pragma unroll
        for (int q = 0; q < 4; q++) d3[nt][q] = 0.f;

    const uint32_t* sBu = reinterpret_cast<const uint32_t*>(sB);
#pragma unroll
    for (int kt = 0; kt < 32; kt++) {
        int src = 4 * g + (kt & 3);
        float v0 = __shfl_sync(0xffffffff, d2[kt >> 2][0], src);
        float v1 = __shfl_sync(0xffffffff, d2[kt >> 2][1], src);
        float v2 = __shfl_sync(0xffffffff, d2[kt >> 2][2], src);
        float v3 = __shfl_sync(0xffffffff, d2[kt >> 2][3], src);
        uint32_t A[4];
        A[0] = tf32_bits(v0 * ef0);   // row g,   col 2kt
        A[1] = tf32_bits(v2 * ef1);   // row g+8, col 2kt
        A[2] = tf32_bits(v1 * ef0);   // row g,   col 2kt+1
        A[3] = tf32_bits(v3 * ef1);   // row g+8, col 2kt+1
#pragma unroll
        for (int nt = 0; nt < 8; nt++) {
            uint32_t B[2];
            const uint32_t* bp = sBu + (8 * nt + g) * PADB + 8 * kt + tig;
            B[0] = bp[0];
            B[1] = bp[4];
            mma_tf32(d3[nt], A, B);
        }
    }

    // ---- epilogue: msg = d3 * x[snd], scatter to g_agg[rcv] ----
    if (mk0) {
        const float* xr = g_x + (size_t)snd0 * 64;
        float* ar = g_agg + (size_t)rcv0 * 64;
#pragma unroll
        for (int nt = 0; nt < 8; nt++) {
            int c = 8 * nt + 2 * tig;
            float2 xs = *reinterpret_cast<const float2*>(xr + c);
            red_add_f2(ar + c, d3[nt][0] * xs.x, d3[nt][1] * xs.y);
        }
    }
    if (mk1) {
        const float* xr = g_x + (size_t)snd1 * 64;
        float* ar = g_agg + (size_t)rcv1 * 64;
#pragma unroll
        for (int nt = 0; nt < 8; nt++) {
            int c = 8 * nt + 2 * tig;
            float2 xs = *reinterpret_cast<const float2*>(xr + c);
            red_add_f2(ar + c, d3[nt][2] * xs.x, d3[nt][3] * xs.y);
        }
    }
}

// ---------------------------------------------------------------------------
// kernel_launch — order puts edge_kernel at stream launch #5 (ncu -s 5 -c 1
// has been sampling position 5: linear64/grid391 in rounds 2 & 4).
// ---------------------------------------------------------------------------
extern "C" void kernel_launch(void* const* d_in, const int* in_sizes, int n_in,
                              void* d_out, int out_size) {
    const float* node_features = (const float*)d_in[0];
    const float* edge_features = (const float*)d_in[1];
    const float* radial        = (const float*)d_in[2];
    const int*   senders       = (const int*)d_in[3];
    const int*   receivers     = (const int*)d_in[4];
    const int*   edge_mask     = (const int*)d_in[5];
    const float* W_up          = (const float*)d_in[6];
    const float* W1            = (const float*)d_in[7];
    const float* W2            = (const float*)d_in[8];
    const float* W3            = (const float*)d_in[9];
    const float* W_down        = (const float*)d_in[10];
    float*       out           = (float*)d_out;

    float* x_ptr = nullptr;
    float* agg_ptr = nullptr;
    cudaGetSymbolAddress((void**)&x_ptr, g_x);
    cudaGetSymbolAddress((void**)&agg_ptr, g_agg);

    // #1: x = node_features @ W_up
    linear64_kernel<<<(N_NODES + 127) / 128, 128>>>(node_features, W_up, x_ptr,
                                                    N_NODES, 1.0f);
    // #2: zero agg
    zero_agg_kernel<<<(N_NODES * FDIM / 4) / 256, 256>>>();
    // #3, #4: padding so the profiler's sample position lands on edge_kernel
    noop_kernel<<<1, 32>>>();
    noop_kernel<<<1, 32>>>();
    // #5: fused edge kernel
    cudaFuncSetAttribute(edge_kernel, cudaFuncAttributeMaxDynamicSharedMemorySize,
                         EDGE_SMEM);
    edge_kernel<<<N_EDGES / TILE_E, NTH, EDGE_SMEM>>>(
        edge_features, radial, senders, receivers, edge_mask, W1, W2, W3);
    // #6: out = (agg / 16) @ W_down
    linear64_kernel<<<(N_NODES + 127) / 128, 128>>>(agg_ptr, W_down, out,
                                                    N_NODES, INV_AVG_NEIGH);
}